// round 11
// baseline (speedup 1.0000x reference)
#include <cuda_runtime.h>
#include <cuda_bf16.h>

#define NN 40000
#define NE 640000
#define ND 128
#define ED 64

typedef unsigned long long u64;

// g_AB PERMUTED: A' cols [0,128): pcol = c0*32 + nt*2 + b (orig col = nt*8+2c0+b)
//                B' cols [128,256): 128 + pcol, b1 folded in.
// g_P PERMUTED same way; g_Bgi k-index permuted to compensate.
__device__ float g_AB[NN * 256];
__device__ float g_P[NN * ND];
__device__ float g_G[NN];
__device__ float g_WtH[ND * 384];
__device__ float g_Wf[ND * 384];
__device__ float g_bf[384];
__device__ uint4 g_Bab[32 * 8 * 32];
__device__ uint4 g_Bgi[48 * 8 * 32];
__device__ uint4 g_Bgh[48 * 8 * 32];
__device__ uint4 g_Bc [16 * 4 * 32];

// ---- packed f32x2 helpers ----
__device__ __forceinline__ u64 pk(float a, float b) {
    u64 d; asm("mov.b64 %0, {%1,%2};" : "=l"(d)
               : "r"(__float_as_uint(a)), "r"(__float_as_uint(b)));
    return d;
}
__device__ __forceinline__ float2 upk(u64 v) {
    unsigned a, b; asm("mov.b64 {%0,%1}, %2;" : "=r"(a), "=r"(b) : "l"(v));
    return make_float2(__uint_as_float(a), __uint_as_float(b));
}
__device__ __forceinline__ u64 fma2(u64 a, u64 b, u64 c) {
    u64 d; asm("fma.rn.f32x2 %0, %1, %2, %3;" : "=l"(d) : "l"(a), "l"(b), "l"(c));
    return d;
}
__device__ __forceinline__ u64 add2(u64 a, u64 b) {
    u64 d; asm("add.rn.f32x2 %0, %1, %2;" : "=l"(d) : "l"(a), "l"(b));
    return d;
}
__device__ __forceinline__ void red4(float* p, float4 v) {
    asm volatile("red.global.add.v4.f32 [%0], {%1, %2, %3, %4};"
                 :: "l"(p), "f"(v.x), "f"(v.y), "f"(v.z), "f"(v.w) : "memory");
}
__device__ __forceinline__ float fsig(float x) { return 1.f / (1.f + __expf(-x)); }
__device__ __forceinline__ float ftanh(float x) {
    float e = __expf(2.f * fabsf(x));
    return copysignf(1.f - 2.f / (e + 1.f), x);
}

// ---- bf16-split helpers ----
__device__ __forceinline__ unsigned bfpack(float x0, float x1) {
    unsigned r; asm("cvt.rn.bf16x2.f32 %0, %1, %2;" : "=r"(r) : "f"(x1), "f"(x0));
    return r;
}
__device__ __forceinline__ void bfsplit(float x0, float x1, unsigned& h, unsigned& lo) {
    h = bfpack(x0, x1);
    __nv_bfloat162 hb = *(__nv_bfloat162*)&h;
    float l0 = x0 - __bfloat162float(hb.x);
    float l1 = x1 - __bfloat162float(hb.y);
    lo = bfpack(l0, l1);
}
__device__ __forceinline__ void mma16(float* c, const unsigned* a, unsigned b0, unsigned b1) {
    asm("mma.sync.aligned.m16n8k16.row.col.f32.bf16.bf16.f32 "
        "{%0,%1,%2,%3},{%4,%5,%6,%7},{%8,%9},{%0,%1,%2,%3};"
        : "+f"(c[0]), "+f"(c[1]), "+f"(c[2]), "+f"(c[3])
        : "r"(a[0]), "r"(a[1]), "r"(a[2]), "r"(a[3]), "r"(b0), "r"(b1));
}
#define ORIGCOL(k) ((((k) >> 1) & 15) * 8 + ((k) >> 5) * 2 + ((k) & 1))

__global__ void k_zero() {
    int i = blockIdx.x * blockDim.x + threadIdx.x;
    if (i < NN * ND / 4)
        reinterpret_cast<float4*>(g_P)[i] = make_float4(0.f, 0.f, 0.f, 0.f);
    if (i < NN / 4)
        reinterpret_cast<float4*>(g_G)[i] = make_float4(0.f, 0.f, 0.f, 0.f);
}

__global__ void k_transH(const float* __restrict__ Whh) {
    int idx = blockIdx.x * blockDim.x + threadIdx.x;
    if (idx < 384 * ND) {
        int k = idx / 384, m = idx % 384;
        g_WtH[idx] = Whh[m * ND + k];
    }
}

__global__ void __launch_bounds__(384) k_fold(const float* __restrict__ W2,
                                              const float* __restrict__ Wih,
                                              const float* __restrict__ b2) {
    __shared__ float sw[ND], sb[ND];
    int q = blockIdx.x, m = threadIdx.x;
    if (m < ND) { sw[m] = W2[q * ND + m]; sb[m] = b2[m]; }
    __syncthreads();
    float acc = 0.f, accb = 0.f;
    const float* wr = Wih + m * ND;
    #pragma unroll 4
    for (int k = 0; k < ND; k++) {
        float w = wr[k];
        acc  = fmaf(sw[k], w, acc);
        accb = fmaf(sb[k], w, accb);
    }
    g_Wf[q * 384 + m] = acc;
    if (q == 0) g_bf[m] = accb;
}

__global__ void k_prep(const float* __restrict__ W1) {
    int i = blockIdx.x * 256 + threadIdx.x;
    int lane = i & 31;
    int n8 = lane >> 2, kq = lane & 3;
    unsigned h0, l0, h1, l1;
    if (i < 8192) {
        int k16 = (i >> 5) & 7, nt = i >> 8;
        int nn = nt * 8 + n8, kb = k16 * 16 + 2 * kq;
        const float* base = (nn < 128) ? (W1 + nn) : (W1 + 128 * 128 + nn - 128);
        bfsplit(base[kb * 128], base[(kb + 1) * 128], h0, l0);
        bfsplit(base[(kb + 8) * 128], base[(kb + 9) * 128], h1, l1);
        g_Bab[i] = make_uint4(h0, h1, l0, l1);
    } else if (i < 8192 + 12288) {
        int ii = i - 8192;
        int k16 = (ii >> 5) & 7, nt = ii >> 8;
        int nn = nt * 8 + n8, kb = k16 * 16 + 2 * kq;
        bfsplit(g_Wf[ORIGCOL(kb) * 384 + nn], g_Wf[ORIGCOL(kb + 1) * 384 + nn], h0, l0);
        bfsplit(g_Wf[ORIGCOL(kb + 8) * 384 + nn], g_Wf[ORIGCOL(kb + 9) * 384 + nn], h1, l1);
        g_Bgi[ii] = make_uint4(h0, h1, l0, l1);
    } else if (i < 8192 + 24576) {
        int ii = i - 8192 - 12288;
        int k16 = (ii >> 5) & 7, nt = ii >> 8;
        int nn = nt * 8 + n8, kb = k16 * 16 + 2 * kq;
        bfsplit(g_WtH[kb * 384 + nn], g_WtH[(kb + 1) * 384 + nn], h0, l0);
        bfsplit(g_WtH[(kb + 8) * 384 + nn], g_WtH[(kb + 9) * 384 + nn], h1, l1);
        g_Bgh[ii] = make_uint4(h0, h1, l0, l1);
    } else {
        int ii = i - 8192 - 24576;
        int idx = ii >> 5;
        int k16 = idx & 3, nt = idx >> 2;
        int nn = nt * 8 + n8, kb = k16 * 16 + 2 * kq;
        const float* base = W1 + 256 * 128 + nn;
        bfsplit(base[kb * 128], base[(kb + 1) * 128], h0, l0);
        bfsplit(base[(kb + 8) * 128], base[(kb + 9) * 128], h1, l1);
        g_Bc[ii] = make_uint4(h0, h1, l0, l1);
    }
}

// nodeAB on tensor cores; stores PERMUTED layout, folds b1 into B'.
__global__ void __launch_bounds__(128) k_nodeAB_t(const float* __restrict__ nf,
                                                  const float* __restrict__ b1) {
    __shared__ unsigned sah[32][68], sal[32][68];
    int t = threadIdx.x, l = t & 31, w = t >> 5;
    int base = blockIdx.x * 32;
    for (int i = t; i < 32 * 64; i += 128) {
        int r = i >> 6, pc = i & 63;
        float2 v = *(const float2*)&nf[(base + r) * ND + pc * 2];
        unsigned h, lo; bfsplit(v.x, v.y, h, lo);
        sah[r][pc] = h; sal[r][pc] = lo;
    }
    __syncthreads();
    float acc[2][8][4];
    #pragma unroll
    for (int m = 0; m < 2; m++)
        #pragma unroll
        for (int n = 0; n < 8; n++)
            #pragma unroll
            for (int x = 0; x < 4; x++) acc[m][n][x] = 0.f;
    int r0 = l >> 2, c0 = l & 3;
    #pragma unroll
    for (int k16 = 0; k16 < 8; k16++) {
        unsigned ah[2][4], al[2][4];
        int kp = k16 * 8 + c0;
        #pragma unroll
        for (int m = 0; m < 2; m++) {
            ah[m][0] = sah[m * 16 + r0][kp];     ah[m][1] = sah[m * 16 + r0 + 8][kp];
            ah[m][2] = sah[m * 16 + r0][kp + 4]; ah[m][3] = sah[m * 16 + r0 + 8][kp + 4];
            al[m][0] = sal[m * 16 + r0][kp];     al[m][1] = sal[m * 16 + r0 + 8][kp];
            al[m][2] = sal[m * 16 + r0][kp + 4]; al[m][3] = sal[m * 16 + r0 + 8][kp + 4];
        }
        #pragma unroll
        for (int n = 0; n < 8; n++) {
            uint4 bv = g_Bab[((w * 8 + n) * 8 + k16) * 32 + l];
            #pragma unroll
            for (int m = 0; m < 2; m++) {
                mma16(acc[m][n], ah[m], bv.x, bv.y);
                mma16(acc[m][n], al[m], bv.x, bv.y);
                mma16(acc[m][n], ah[m], bv.z, bv.w);
            }
        }
    }
    #pragma unroll
    for (int m = 0; m < 2; m++)
        #pragma unroll
        for (int n = 0; n < 8; n++) {
            int ntg = w * 8 + n;
            int row = base + m * 16 + r0;
            int nt = ntg & 15;
            int pc = (ntg < 16 ? 0 : 128) + c0 * 32 + nt * 2;
            float2 add = make_float2(0.f, 0.f);
            if (ntg >= 16) add = *(const float2*)&b1[nt * 8 + 2 * c0];
            *(float2*)&g_AB[row * 256 + pc] =
                make_float2(acc[m][n][0] + add.x, acc[m][n][1] + add.y);
            *(float2*)&g_AB[(row + 8) * 256 + pc] =
                make_float2(acc[m][n][2] + add.x, acc[m][n][3] + add.y);
        }
}

// Edge kernel on tensor cores: 2-warp pair per 16-edge tile.
// Warp wp owns nt = wp*8..wp*8+7 (permuted cols c0*32 + wp*16 + 0..15).
// acc[8][4] = 32 regs; LN stats exchanged via smem + named barrier.
__global__ void __launch_bounds__(128, 6) k_edge_t(
    const float* __restrict__ ef, const int* __restrict__ ei,
    const float* __restrict__ lng, const float* __restrict__ lnb,
    const float* __restrict__ gw, const float* __restrict__ gb) {
    __shared__ unsigned shi[2][16 * 36], slo[2][16 * 36];
    __shared__ float sg[2][16];
    __shared__ u64 sredS[2][2][8], sredQ[2][2][8];
    __shared__ float s_ln[256];   // lng | lnb (original col order)
    int t = threadIdx.x, l = t & 31, w = t >> 5;
    int pr = w >> 1, wp = w & 1;
    s_ln[t] = lng[t];
    s_ln[128 + t] = lnb[t];
    __syncthreads();
    unsigned* myhi = shi[pr];
    unsigned* mylo = slo[pr];
    int r0 = l >> 2, c0 = l & 3;
    float gb0 = gb[0];
    int barid = 1 + pr;

    for (int e0 = (blockIdx.x * 2 + pr) * 16; e0 < NE; e0 += gridDim.x * 32) {
        // guard: prior tile's sg/shi readers (other warp) must be done
        asm volatile("bar.sync %0, 64;" :: "r"(barid) : "memory");
        int sv  = ei[e0 + (l & 15)];
        int dvv = ei[NE + e0 + (l & 15)];

        // stage 8 edges per warp: e = wp*8 + r0, quarter q = c0 (k = q*16..q*16+15)
        {
            int e = wp * 8 + r0;
            const float4* src4 = (const float4*)(ef + (size_t)(e0 + e) * ED) + c0 * 4;
            const float4* gw4 = (const float4*)gw + c0 * 4;
            float gd = 0.f;
            #pragma unroll
            for (int i = 0; i < 4; i++) {
                float4 v = src4[i];
                float4 g4 = gw4[i];
                gd = fmaf(v.x, g4.x, gd); gd = fmaf(v.y, g4.y, gd);
                gd = fmaf(v.z, g4.z, gd); gd = fmaf(v.w, g4.w, gd);
                unsigned h0, l0, h1, l1;
                bfsplit(v.x, v.y, h0, l0);
                bfsplit(v.z, v.w, h1, l1);
                int kp = e * 36 + c0 * 8 + 2 * i;
                myhi[kp] = h0; myhi[kp + 1] = h1;
                mylo[kp] = l0; mylo[kp + 1] = l1;
            }
            gd += __shfl_xor_sync(0xffffffffu, gd, 1);
            gd += __shfl_xor_sync(0xffffffffu, gd, 2);
            if (c0 == 0) sg[pr][e] = fsig(gd + gb0);
        }
        asm volatile("bar.sync %0, 64;" :: "r"(barid) : "memory");

        // gather base (b1 folded into B'): this warp's 16-col slices
        float acc[8][4];
        int d0 = __shfl_sync(0xffffffffu, dvv, r0);
        int d1 = __shfl_sync(0xffffffffu, dvv, r0 + 8);
        {
            int s0 = __shfl_sync(0xffffffffu, sv, r0);
            int s1 = __shfl_sync(0xffffffffu, sv, r0 + 8);
            int off = c0 * 32 + wp * 16;
            const float4* A0 = (const float4*)(g_AB + (size_t)s0 * 256 + off);
            const float4* B0 = (const float4*)(g_AB + (size_t)d0 * 256 + 128 + off);
            const float4* A1 = (const float4*)(g_AB + (size_t)s1 * 256 + off);
            const float4* B1 = (const float4*)(g_AB + (size_t)d1 * 256 + 128 + off);
            #pragma unroll
            for (int i = 0; i < 4; i++) {
                float4 a = A0[i], b = B0[i];
                acc[2 * i][0]     = a.x + b.x; acc[2 * i][1]     = a.y + b.y;
                acc[2 * i + 1][0] = a.z + b.z; acc[2 * i + 1][1] = a.w + b.w;
                float4 a2 = A1[i], b2 = B1[i];
                acc[2 * i][2]     = a2.x + b2.x; acc[2 * i][3]     = a2.y + b2.y;
                acc[2 * i + 1][2] = a2.z + b2.z; acc[2 * i + 1][3] = a2.w + b2.w;
            }
        }

        // h += ef @ W1c on tensor cores (this warp's 8 n-tiles)
        #pragma unroll
        for (int k16 = 0; k16 < 4; k16++) {
            unsigned ah[4], al[4];
            int kp = k16 * 8 + c0;
            ah[0] = myhi[r0 * 36 + kp];         ah[1] = myhi[(r0 + 8) * 36 + kp];
            ah[2] = myhi[r0 * 36 + kp + 4];     ah[3] = myhi[(r0 + 8) * 36 + kp + 4];
            al[0] = mylo[r0 * 36 + kp];         al[1] = mylo[(r0 + 8) * 36 + kp];
            al[2] = mylo[r0 * 36 + kp + 4];     al[3] = mylo[(r0 + 8) * 36 + kp + 4];
            #pragma unroll
            for (int nt = 0; nt < 8; nt++) {
                uint4 bv = g_Bc[((wp * 8 + nt) * 4 + k16) * 32 + l];
                mma16(acc[nt], ah, bv.x, bv.y);
                mma16(acc[nt], al, bv.x, bv.y);
                mma16(acc[nt], ah, bv.z, bv.w);
            }
        }

        // LN partials over this warp's 64 cols
        u64 s = 0, q2 = 0;
        #pragma unroll
        for (int nt = 0; nt < 8; nt++) {
            u64 v0 = pk(acc[nt][0], acc[nt][2]);
            u64 v1 = pk(acc[nt][1], acc[nt][3]);
            s = add2(s, add2(v0, v1));
            q2 = fma2(v0, v0, q2);
            q2 = fma2(v1, v1, q2);
        }
        s  = add2(s,  __shfl_xor_sync(0xffffffffu, s, 1));
        s  = add2(s,  __shfl_xor_sync(0xffffffffu, s, 2));
        q2 = add2(q2, __shfl_xor_sync(0xffffffffu, q2, 1));
        q2 = add2(q2, __shfl_xor_sync(0xffffffffu, q2, 2));
        if (c0 == 0) { sredS[pr][wp][r0] = s; sredQ[pr][wp][r0] = q2; }
        asm volatile("bar.sync %0, 64;" :: "r"(barid) : "memory");
        s  = add2(s,  sredS[pr][wp ^ 1][r0]);
        q2 = add2(q2, sredQ[pr][wp ^ 1][r0]);

        float2 sf = upk(s), qf = upk(q2);
        float mu0 = sf.x * (1.f / ND), mu1 = sf.y * (1.f / ND);
        float rs0 = rsqrtf(qf.x * (1.f / ND) - mu0 * mu0 + 1e-5f);
        float rs1 = rsqrtf(qf.y * (1.f / ND) - mu1 * mu1 + 1e-5f);
        float g0 = sg[pr][r0], g1 = sg[pr][r0 + 8];

        // normalize, relu, gate, scatter (permuted g_P)
        #pragma unroll
        for (int i = 0; i < 4; i++) {
            int nt = 2 * i;
            int ntg = wp * 8 + nt;
            float2 lg_a = *(const float2*)&s_ln[ntg * 8 + 2 * c0];
            float2 lb_a = *(const float2*)&s_ln[128 + ntg * 8 + 2 * c0];
            float2 lg_b = *(const float2*)&s_ln[(ntg + 1) * 8 + 2 * c0];
            float2 lb_b = *(const float2*)&s_ln[128 + (ntg + 1) * 8 + 2 * c0];
            float4 o0, o1;
            o0.x = fmaxf((acc[nt][0]     - mu0) * rs0 * lg_a.x + lb_a.x, 0.f) * g0;
            o0.y = fmaxf((acc[nt][1]     - mu0) * rs0 * lg_a.y + lb_a.y, 0.f) * g0;
            o0.z = fmaxf((acc[nt + 1][0] - mu0) * rs0 * lg_b.x + lb_b.x, 0.f) * g0;
            o0.w = fmaxf((acc[nt + 1][1] - mu0) * rs0 * lg_b.y + lb_b.y, 0.f) * g0;
            o1.x = fmaxf((acc[nt][2]     - mu1) * rs1 * lg_a.x + lb_a.x, 0.f) * g1;
            o1.y = fmaxf((acc[nt][3]     - mu1) * rs1 * lg_a.y + lb_a.y, 0.f) * g1;
            o1.z = fmaxf((acc[nt + 1][2] - mu1) * rs1 * lg_b.x + lb_b.x, 0.f) * g1;
            o1.w = fmaxf((acc[nt + 1][3] - mu1) * rs1 * lg_b.y + lb_b.y, 0.f) * g1;
            int off = c0 * 32 + wp * 16 + nt * 2;
            red4(&g_P[(size_t)d0 * ND + off], o0);
            red4(&g_P[(size_t)d1 * ND + off], o1);
        }
        if (wp == 0 && l < 16) atomicAdd(&g_G[dvv], sg[pr][l]);
    }
}

// GRU on tensor cores (g_Bgi k-permuted to match permuted g_P).
__global__ void __launch_bounds__(128) k_gru_t(const float* __restrict__ nf,
                                               const float* __restrict__ bih,
                                               const float* __restrict__ bhh,
                                               float* __restrict__ out) {
    __shared__ unsigned sph[16][68], spl[16][68], snh[16][68], snl[16][68];
    __shared__ float snraw[16][132];
    __shared__ float sgi[128][49];
    int t = threadIdx.x, l = t & 31, w = t >> 5;
    int base = blockIdx.x * 16;
    for (int i = t; i < 16 * 64; i += 128) {
        int r = i >> 6, pc = i & 63;
        float2 vp = *(const float2*)&g_P[(base + r) * ND + pc * 2];
        float2 vn = *(const float2*)&nf[(base + r) * ND + pc * 2];
        unsigned h, lo;
        bfsplit(vp.x, vp.y, h, lo); sph[r][pc] = h; spl[r][pc] = lo;
        bfsplit(vn.x, vn.y, h, lo); snh[r][pc] = h; snl[r][pc] = lo;
        snraw[r][pc * 2] = vn.x; snraw[r][pc * 2 + 1] = vn.y;
    }
    __syncthreads();
    int r0 = l >> 2, c0 = l & 3;
    float acc[12][4];

    #pragma unroll
    for (int j = 0; j < 12; j++)
        #pragma unroll
        for (int x = 0; x < 4; x++) acc[j][x] = 0.f;
    #pragma unroll
    for (int k16 = 0; k16 < 8; k16++) {
        unsigned ah[4], al[4];
        int kp = k16 * 8 + c0;
        ah[0] = sph[r0][kp];     ah[1] = sph[r0 + 8][kp];
        ah[2] = sph[r0][kp + 4]; ah[3] = sph[r0 + 8][kp + 4];
        al[0] = spl[r0][kp];     al[1] = spl[r0 + 8][kp];
        al[2] = spl[r0][kp + 4]; al[3] = spl[r0 + 8][kp + 4];
        #pragma unroll
        for (int j = 0; j < 12; j++) {
            int nt = (j >> 2) * 16 + w * 4 + (j & 3);
            uint4 bvv = g_Bgi[(nt * 8 + k16) * 32 + l];
            mma16(acc[j], ah, bvv.x, bvv.y);
            mma16(acc[j], al, bvv.x, bvv.y);
            mma16(acc[j], ah, bvv.z, bvv.w);
        }
    }
    #pragma unroll
    for (int j = 0; j < 12; j++)
        #pragma unroll
        for (int x = 0; x < 4; x++) sgi[t][j * 4 + x] = acc[j][x];

    #pragma unroll
    for (int j = 0; j < 12; j++)
        #pragma unroll
        for (int x = 0; x < 4; x++) acc[j][x] = 0.f;
    #pragma unroll
    for (int k16 = 0; k16 < 8; k16++) {
        unsigned ah[4], al[4];
        int kp = k16 * 8 + c0;
        ah[0] = snh[r0][kp];     ah[1] = snh[r0 + 8][kp];
        ah[2] = snh[r0][kp + 4]; ah[3] = snh[r0 + 8][kp + 4];
        al[0] = snl[r0][kp];     al[1] = snl[r0 + 8][kp];
        al[2] = snl[r0][kp + 4]; al[3] = snl[r0 + 8][kp + 4];
        #pragma unroll
        for (int j = 0; j < 12; j++) {
            int nt = (j >> 2) * 16 + w * 4 + (j & 3);
            uint4 bvv = g_Bgh[(nt * 8 + k16) * 32 + l];
            mma16(acc[j], ah, bvv.x, bvv.y);
            mma16(acc[j], al, bvv.x, bvv.y);
            mma16(acc[j], ah, bvv.z, bvv.w);
        }
    }

    float G0 = g_G[base + r0], G1 = g_G[base + r0 + 8];
    #pragma unroll
    for (int j = 0; j < 4; j++) {
        int colg = w * 32 + j * 8 + 2 * c0;
        float2 o0, o1;
        #pragma unroll
        for (int b = 0; b < 2; b++) {
            int col = colg + b;
            float bfr = g_bf[col], bfz = g_bf[128 + col], bfn = g_bf[256 + col];
            float bir = bih[col], biz = bih[128 + col], bin = bih[256 + col];
            float bhr = bhh[col], bhz = bhh[128 + col], bhn = bhh[256 + col];
            {
                float gir = sgi[t][j * 4 + b]       + bir + G0 * bfr;
                float giz = sgi[t][(j + 4) * 4 + b] + biz + G0 * bfz;
                float gin = sgi[t][(j + 8) * 4 + b] + bin + G0 * bfn;
                float ghr = acc[j][b] + bhr, ghz = acc[j + 4][b] + bhz, ghn = acc[j + 8][b] + bhn;
                float rr = fsig(gir + ghr), zz = fsig(giz + ghz);
                float nv = ftanh(gin + rr * ghn);
                float xo = (1.f - zz) * nv + zz * snraw[r0][col];
                if (b) o0.y = xo; else o0.x = xo;
            }
            {
                float gir = sgi[t][j * 4 + b + 2]       + bir + G1 * bfr;
                float giz = sgi[t][(j + 4) * 4 + b + 2] + biz + G1 * bfz;
                float gin = sgi[t][(j + 8) * 4 + b + 2] + bin + G1 * bfn;
                float ghr = acc[j][b + 2] + bhr, ghz = acc[j + 4][b + 2] + bhz, ghn = acc[j + 8][b + 2] + bhn;
                float rr = fsig(gir + ghr), zz = fsig(giz + ghz);
                float nv = ftanh(gin + rr * ghn);
                float xo = (1.f - zz) * nv + zz * snraw[r0 + 8][col];
                if (b) o1.y = xo; else o1.x = xo;
            }
        }
        *(float2*)&out[(base + r0) * ND + colg]     = o0;
        *(float2*)&out[(base + r0 + 8) * ND + colg] = o1;
    }
}

extern "C" void kernel_launch(void* const* d_in, const int* in_sizes, int n_in,
                              void* d_out, int out_size) {
    const float* nf  = (const float*)d_in[0];
    const int*   ei  = (const int*)d_in[1];
    const float* ef  = (const float*)d_in[2];
    const float* W1  = (const float*)d_in[3];
    const float* b1  = (const float*)d_in[4];
    const float* lng = (const float*)d_in[5];
    const float* lnb = (const float*)d_in[6];
    const float* W2  = (const float*)d_in[7];
    const float* b2  = (const float*)d_in[8];
    const float* gw  = (const float*)d_in[9];
    const float* gb  = (const float*)d_in[10];
    const float* Wih = (const float*)d_in[11];
    const float* bih = (const float*)d_in[12];
    const float* Whh = (const float*)d_in[13];
    const float* bhh = (const float*)d_in[14];
    float* out = (float*)d_out;

    k_zero<<<(NN * ND / 4 + 255) / 256, 256>>>();
    k_transH<<<(384 * ND + 255) / 256, 256>>>(Whh);
    k_fold<<<ND, 384>>>(W2, Wih, b2);
    k_prep<<<136, 256>>>(W1);
    k_nodeAB_t<<<NN / 32, 128>>>(nf, b1);
    k_edge_t<<<2368, 128>>>(ef, ei, lng, lnb, gw, gb);
    k_gru_t<<<NN / 16, 128>>>(nf, bih, bhh, out);
}

// round 12
// speedup vs baseline: 1.1434x; 1.1434x over previous
#include <cuda_runtime.h>
#include <cuda_bf16.h>

#define NN 40000
#define NE 640000
#define ND 128
#define ED 64

typedef unsigned long long u64;

// Scratch (static device allocations — allowed). Plain (non-permuted) layouts.
__device__ float g_AB[NN * 256];      // per-node A|B = nf@W1a | nf@W1b
__device__ float g_P[NN * ND];        // scatter: sum of gate*relu(ln(h))
__device__ float g_G[NN];             // scatter: sum of gates
__device__ float g_WtH[ND * 384];
__device__ float g_Wf[ND * 384];
__device__ float g_bf[384];
// Pre-packed bf16-split B fragments for mma.m16n8k16: uint4{bh0,bh1,bl0,bl1}
__device__ uint4 g_Bab[32 * 8 * 32];
__device__ uint4 g_Bgi[48 * 8 * 32];
__device__ uint4 g_Bgh[48 * 8 * 32];

// ---- packed f32x2 helpers ----
__device__ __forceinline__ u64 pk(float a, float b) {
    u64 d; asm("mov.b64 %0, {%1,%2};" : "=l"(d)
               : "r"(__float_as_uint(a)), "r"(__float_as_uint(b)));
    return d;
}
__device__ __forceinline__ float2 upk(u64 v) {
    unsigned a, b; asm("mov.b64 {%0,%1}, %2;" : "=r"(a), "=r"(b) : "l"(v));
    return make_float2(__uint_as_float(a), __uint_as_float(b));
}
__device__ __forceinline__ u64 fma2(u64 a, u64 b, u64 c) {
    u64 d; asm("fma.rn.f32x2 %0, %1, %2, %3;" : "=l"(d) : "l"(a), "l"(b), "l"(c));
    return d;
}
__device__ __forceinline__ u64 add2(u64 a, u64 b) {
    u64 d; asm("add.rn.f32x2 %0, %1, %2;" : "=l"(d) : "l"(a), "l"(b));
    return d;
}
__device__ __forceinline__ void red4(float* p, float4 v) {
    asm volatile("red.global.add.v4.f32 [%0], {%1, %2, %3, %4};"
                 :: "l"(p), "f"(v.x), "f"(v.y), "f"(v.z), "f"(v.w) : "memory");
}
__device__ __forceinline__ float fsig(float x) { return 1.f / (1.f + __expf(-x)); }
__device__ __forceinline__ float ftanh(float x) {
    float e = __expf(2.f * fabsf(x));
    return copysignf(1.f - 2.f / (e + 1.f), x);
}

// ---- bf16-split helpers ----
__device__ __forceinline__ unsigned bfpack(float x0, float x1) {
    unsigned r; asm("cvt.rn.bf16x2.f32 %0, %1, %2;" : "=r"(r) : "f"(x1), "f"(x0));
    return r;
}
__device__ __forceinline__ void bfsplit(float x0, float x1, unsigned& h, unsigned& lo) {
    h = bfpack(x0, x1);
    __nv_bfloat162 hb = *(__nv_bfloat162*)&h;
    float l0 = x0 - __bfloat162float(hb.x);
    float l1 = x1 - __bfloat162float(hb.y);
    lo = bfpack(l0, l1);
}
__device__ __forceinline__ void mma16(float* c, const unsigned* a, unsigned b0, unsigned b1) {
    asm("mma.sync.aligned.m16n8k16.row.col.f32.bf16.bf16.f32 "
        "{%0,%1,%2,%3},{%4,%5,%6,%7},{%8,%9},{%0,%1,%2,%3};"
        : "+f"(c[0]), "+f"(c[1]), "+f"(c[2]), "+f"(c[3])
        : "r"(a[0]), "r"(a[1]), "r"(a[2]), "r"(a[3]), "r"(b0), "r"(b1));
}

__global__ void k_zero() {
    int i = blockIdx.x * blockDim.x + threadIdx.x;
    if (i < NN * ND / 4)
        reinterpret_cast<float4*>(g_P)[i] = make_float4(0.f, 0.f, 0.f, 0.f);
    if (i < NN / 4)
        reinterpret_cast<float4*>(g_G)[i] = make_float4(0.f, 0.f, 0.f, 0.f);
}

__global__ void k_transH(const float* __restrict__ Whh) {
    int idx = blockIdx.x * blockDim.x + threadIdx.x;
    if (idx < 384 * ND) {
        int k = idx / 384, m = idx % 384;
        g_WtH[idx] = Whh[m * ND + k];
    }
}

// Fold W2 into GRU input weights
__global__ void __launch_bounds__(384) k_fold(const float* __restrict__ W2,
                                              const float* __restrict__ Wih,
                                              const float* __restrict__ b2) {
    __shared__ float sw[ND], sb[ND];
    int q = blockIdx.x, m = threadIdx.x;
    if (m < ND) { sw[m] = W2[q * ND + m]; sb[m] = b2[m]; }
    __syncthreads();
    float acc = 0.f, accb = 0.f;
    const float* wr = Wih + m * ND;
    #pragma unroll 4
    for (int k = 0; k < ND; k++) {
        float w = wr[k];
        acc  = fmaf(sw[k], w, acc);
        accb = fmaf(sb[k], w, accb);
    }
    g_Wf[q * 384 + m] = acc;
    if (q == 0) g_bf[m] = accb;
}

// Pack B fragments (bf16 hi/lo) for the three dense GEMM weight matrices.
__global__ void k_prep(const float* __restrict__ W1) {
    int i = blockIdx.x * 256 + threadIdx.x;   // 0..32767
    int lane = i & 31;
    int n8 = lane >> 2, kq = lane & 3;
    unsigned h0, l0, h1, l1;
    if (i < 8192) {                            // g_Bab from W1 rows 0..255
        int k16 = (i >> 5) & 7, nt = i >> 8;
        int nn = nt * 8 + n8, kb = k16 * 16 + 2 * kq;
        const float* base = (nn < 128) ? (W1 + nn) : (W1 + 128 * 128 + nn - 128);
        bfsplit(base[kb * 128], base[(kb + 1) * 128], h0, l0);
        bfsplit(base[(kb + 8) * 128], base[(kb + 9) * 128], h1, l1);
        g_Bab[i] = make_uint4(h0, h1, l0, l1);
    } else if (i < 8192 + 12288) {             // g_Bgi from g_Wf [k][384]
        int ii = i - 8192;
        int k16 = (ii >> 5) & 7, nt = ii >> 8;
        int nn = nt * 8 + n8, kb = k16 * 16 + 2 * kq;
        bfsplit(g_Wf[kb * 384 + nn], g_Wf[(kb + 1) * 384 + nn], h0, l0);
        bfsplit(g_Wf[(kb + 8) * 384 + nn], g_Wf[(kb + 9) * 384 + nn], h1, l1);
        g_Bgi[ii] = make_uint4(h0, h1, l0, l1);
    } else {                                   // g_Bgh from g_WtH [k][384]
        int ii = i - 8192 - 12288;
        int k16 = (ii >> 5) & 7, nt = ii >> 8;
        int nn = nt * 8 + n8, kb = k16 * 16 + 2 * kq;
        bfsplit(g_WtH[kb * 384 + nn], g_WtH[(kb + 1) * 384 + nn], h0, l0);
        bfsplit(g_WtH[(kb + 8) * 384 + nn], g_WtH[(kb + 9) * 384 + nn], h1, l1);
        g_Bgh[ii] = make_uint4(h0, h1, l0, l1);
    }
}

// nodeAB on tensor cores: 32 nodes/block, warp owns 64 cols of 256.
__global__ void __launch_bounds__(128) k_nodeAB_t(const float* __restrict__ nf) {
    __shared__ unsigned sah[32][68], sal[32][68];
    int t = threadIdx.x, l = t & 31, w = t >> 5;
    int base = blockIdx.x * 32;
    for (int i = t; i < 32 * 64; i += 128) {
        int r = i >> 6, pc = i & 63;
        float2 v = *(const float2*)&nf[(base + r) * ND + pc * 2];
        unsigned h, lo; bfsplit(v.x, v.y, h, lo);
        sah[r][pc] = h; sal[r][pc] = lo;
    }
    __syncthreads();
    float acc[2][8][4];
    #pragma unroll
    for (int m = 0; m < 2; m++)
        #pragma unroll
        for (int n = 0; n < 8; n++)
            #pragma unroll
            for (int x = 0; x < 4; x++) acc[m][n][x] = 0.f;
    int r0 = l >> 2, c0 = l & 3;
    #pragma unroll
    for (int k16 = 0; k16 < 8; k16++) {
        unsigned ah[2][4], al[2][4];
        int kp = k16 * 8 + c0;
        #pragma unroll
        for (int m = 0; m < 2; m++) {
            ah[m][0] = sah[m * 16 + r0][kp];     ah[m][1] = sah[m * 16 + r0 + 8][kp];
            ah[m][2] = sah[m * 16 + r0][kp + 4]; ah[m][3] = sah[m * 16 + r0 + 8][kp + 4];
            al[m][0] = sal[m * 16 + r0][kp];     al[m][1] = sal[m * 16 + r0 + 8][kp];
            al[m][2] = sal[m * 16 + r0][kp + 4]; al[m][3] = sal[m * 16 + r0 + 8][kp + 4];
        }
        #pragma unroll
        for (int n = 0; n < 8; n++) {
            uint4 bv = g_Bab[((w * 8 + n) * 8 + k16) * 32 + l];
            #pragma unroll
            for (int m = 0; m < 2; m++) {
                mma16(acc[m][n], ah[m], bv.x, bv.y);
                mma16(acc[m][n], al[m], bv.x, bv.y);
                mma16(acc[m][n], ah[m], bv.z, bv.w);
            }
        }
    }
    #pragma unroll
    for (int m = 0; m < 2; m++)
        #pragma unroll
        for (int n = 0; n < 8; n++) {
            int row = base + m * 16 + r0;
            int col = w * 64 + n * 8 + 2 * c0;
            *(float2*)&g_AB[row * 256 + col]       = make_float2(acc[m][n][0], acc[m][n][1]);
            *(float2*)&g_AB[(row + 8) * 256 + col] = make_float2(acc[m][n][2], acc[m][n][3]);
        }
}

// Edge kernel (fp32 FFMA2): warp-autonomous, 8 edges (4 packed pairs) per tile,
// 4 cols/thread. Gather issued FIRST; staging+gate cover its latency.
// 24 warps/SM via __launch_bounds__(128,6).
__global__ void __launch_bounds__(128, 6) k_edge(
    const float* __restrict__ ef, const int* __restrict__ ei,
    const float* __restrict__ W1, const float* __restrict__ b1,
    const float* __restrict__ lng, const float* __restrict__ lnb,
    const float* __restrict__ gw, const float* __restrict__ gb) {
    __shared__ __align__(16) float sef[4][4 * 132];   // [warp][pair*132 + k*2+half]
    __shared__ float sg[4][8];
    int t = threadIdx.x, l = t & 31, w = t >> 5;
    float* mysef = sef[w];
    float4 b1v = *(const float4*)&b1[4 * l];
    float4 gv  = *(const float4*)&lng[4 * l];
    float4 bv  = *(const float4*)&lnb[4 * l];
    float gb0 = gb[0];
    const float4* WC = (const float4*)(W1 + 256 * ND) + l;   // row k at WC[k*32]

    for (int e0 = (blockIdx.x * 4 + w) * 8; e0 < NE; e0 += gridDim.x * 32) {
        __syncwarp();
        int sv = ei[e0 + (l & 7)];
        int dv = ei[NE + e0 + (l & 7)];

        // EARLY gather: acc init = b1 + A[src] + B[dst] (issued before staging/gate)
        u64 acc[4][4];
        #pragma unroll
        for (int p = 0; p < 4; p++) {
            int s0 = __shfl_sync(0xffffffffu, sv, 2 * p);
            int s1 = __shfl_sync(0xffffffffu, sv, 2 * p + 1);
            int d0 = __shfl_sync(0xffffffffu, dv, 2 * p);
            int d1 = __shfl_sync(0xffffffffu, dv, 2 * p + 1);
            float4 A0 = *(const float4*)&g_AB[(size_t)s0 * 256 + 4 * l];
            float4 A1 = *(const float4*)&g_AB[(size_t)s1 * 256 + 4 * l];
            float4 B0 = *(const float4*)&g_AB[(size_t)d0 * 256 + ND + 4 * l];
            float4 B1 = *(const float4*)&g_AB[(size_t)d1 * 256 + ND + 4 * l];
            acc[p][0] = pk(b1v.x + A0.x + B0.x, b1v.x + A1.x + B1.x);
            acc[p][1] = pk(b1v.y + A0.y + B0.y, b1v.y + A1.y + B1.y);
            acc[p][2] = pk(b1v.z + A0.z + B0.z, b1v.z + A1.z + B1.z);
            acc[p][3] = pk(b1v.w + A0.w + B0.w, b1v.w + A1.w + B1.w);
        }

        // stage 8 edges pair-packed: [p][k*2+h]
        #pragma unroll
        for (int q = 0; q < 4; q++) {
            float2 v0 = *(const float2*)&ef[(size_t)(e0 + 2 * q) * ED + 2 * l];
            float2 v1 = *(const float2*)&ef[(size_t)(e0 + 2 * q + 1) * ED + 2 * l];
            *(float4*)&mysef[q * 132 + 4 * l] = make_float4(v0.x, v1.x, v0.y, v1.y);
        }
        __syncwarp();

        // gate: 4 lanes/edge, interleaved k (conflict-free LDS)
        {
            int e = l >> 2, part = l & 3, h = e & 1, p = e >> 1;
            const float* base = &mysef[p * 132 + h];
            float gd = 0.f;
            #pragma unroll
            for (int i = 0; i < 16; i++) {
                int k = part + 4 * i;
                gd = fmaf(base[k * 2], gw[k], gd);
            }
            gd += __shfl_xor_sync(0xffffffffu, gd, 1);
            gd += __shfl_xor_sync(0xffffffffu, gd, 2);
            if (part == 0) sg[w][e] = fsig(gd + gb0);
        }

        // h += ef @ W1c : 1 LDS.128 broadcast feeds 8 FFMA2 (4 cols x 2 k)
        #pragma unroll 1
        for (int k = 0; k < ED; k += 2) {
            float4 w0 = WC[k * 32];
            float4 w1 = WC[(k + 1) * 32];
            u64 w0x = pk(w0.x, w0.x), w0y = pk(w0.y, w0.y);
            u64 w0z = pk(w0.z, w0.z), w0w = pk(w0.w, w0.w);
            u64 w1x = pk(w1.x, w1.x), w1y = pk(w1.y, w1.y);
            u64 w1z = pk(w1.z, w1.z), w1w = pk(w1.w, w1.w);
            #pragma unroll
            for (int p = 0; p < 4; p++) {
                ulonglong2 xx = *(const ulonglong2*)&mysef[p * 132 + 2 * k];
                acc[p][0] = fma2(xx.x, w0x, acc[p][0]);
                acc[p][1] = fma2(xx.x, w0y, acc[p][1]);
                acc[p][2] = fma2(xx.x, w0z, acc[p][2]);
                acc[p][3] = fma2(xx.x, w0w, acc[p][3]);
                acc[p][0] = fma2(xx.y, w1x, acc[p][0]);
                acc[p][1] = fma2(xx.y, w1y, acc[p][1]);
                acc[p][2] = fma2(xx.y, w1z, acc[p][2]);
                acc[p][3] = fma2(xx.y, w1w, acc[p][3]);
            }
        }

        // warp-local LayerNorm stats (pre-add 4 cols, packed 2 edges)
        u64 sum[4], sq[4];
        #pragma unroll
        for (int p = 0; p < 4; p++) {
            sum[p] = add2(add2(acc[p][0], acc[p][1]), add2(acc[p][2], acc[p][3]));
            u64 q2 = fma2(acc[p][0], acc[p][0], (u64)0);
            q2 = fma2(acc[p][1], acc[p][1], q2);
            q2 = fma2(acc[p][2], acc[p][2], q2);
            sq[p] = fma2(acc[p][3], acc[p][3], q2);
        }
        #pragma unroll
        for (int o = 16; o; o >>= 1) {
            #pragma unroll
            for (int p = 0; p < 4; p++) {
                sum[p] = add2(sum[p], __shfl_xor_sync(0xffffffffu, sum[p], o));
                sq[p]  = add2(sq[p],  __shfl_xor_sync(0xffffffffu, sq[p],  o));
            }
        }
        __syncwarp();

        // normalize, relu, gate, vectored reduce-scatter
        #pragma unroll
        for (int p = 0; p < 4; p++) {
            float2 s = upk(sum[p]), s2 = upk(sq[p]);
            float mu0 = s.x * (1.f / ND), mu1 = s.y * (1.f / ND);
            float r0 = rsqrtf(s2.x * (1.f / ND) - mu0 * mu0 + 1e-5f);
            float r1 = rsqrtf(s2.y * (1.f / ND) - mu1 * mu1 + 1e-5f);
            float g0 = sg[w][2 * p], g1 = sg[w][2 * p + 1];
            int d0 = __shfl_sync(0xffffffffu, dv, 2 * p);
            int d1 = __shfl_sync(0xffffffffu, dv, 2 * p + 1);
            float2 h0 = upk(acc[p][0]), h1 = upk(acc[p][1]);
            float2 h2 = upk(acc[p][2]), h3 = upk(acc[p][3]);
            float4 o0, o1;
            o0.x = fmaxf((h0.x - mu0) * r0 * gv.x + bv.x, 0.f) * g0;
            o0.y = fmaxf((h1.x - mu0) * r0 * gv.y + bv.y, 0.f) * g0;
            o0.z = fmaxf((h2.x - mu0) * r0 * gv.z + bv.z, 0.f) * g0;
            o0.w = fmaxf((h3.x - mu0) * r0 * gv.w + bv.w, 0.f) * g0;
            o1.x = fmaxf((h0.y - mu1) * r1 * gv.x + bv.x, 0.f) * g1;
            o1.y = fmaxf((h1.y - mu1) * r1 * gv.y + bv.y, 0.f) * g1;
            o1.z = fmaxf((h2.y - mu1) * r1 * gv.z + bv.z, 0.f) * g1;
            o1.w = fmaxf((h3.y - mu1) * r1 * gv.w + bv.w, 0.f) * g1;
            red4(&g_P[(size_t)d0 * ND + 4 * l], o0);
            red4(&g_P[(size_t)d1 * ND + 4 * l], o1);
        }
        if (l < 8) atomicAdd(&g_G[dv], sg[w][l]);
    }
}

// GRU on tensor cores: 16 nodes/block; warp owns cols [w*32, w*32+32) of each gate.
__global__ void __launch_bounds__(128) k_gru_t(const float* __restrict__ nf,
                                               const float* __restrict__ bih,
                                               const float* __restrict__ bhh,
                                               float* __restrict__ out) {
    __shared__ unsigned sph[16][68], spl[16][68], snh[16][68], snl[16][68];
    __shared__ float snraw[16][132];
    __shared__ float sgi[128][49];
    int t = threadIdx.x, l = t & 31, w = t >> 5;
    int base = blockIdx.x * 16;
    for (int i = t; i < 16 * 64; i += 128) {
        int r = i >> 6, pc = i & 63;
        float2 vp = *(const float2*)&g_P[(base + r) * ND + pc * 2];
        float2 vn = *(const float2*)&nf[(base + r) * ND + pc * 2];
        unsigned h, lo;
        bfsplit(vp.x, vp.y, h, lo); sph[r][pc] = h; spl[r][pc] = lo;
        bfsplit(vn.x, vn.y, h, lo); snh[r][pc] = h; snl[r][pc] = lo;
        snraw[r][pc * 2] = vn.x; snraw[r][pc * 2 + 1] = vn.y;
    }
    __syncthreads();
    int r0 = l >> 2, c0 = l & 3;
    float acc[12][4];

    #pragma unroll
    for (int j = 0; j < 12; j++)
        #pragma unroll
        for (int x = 0; x < 4; x++) acc[j][x] = 0.f;
    #pragma unroll
    for (int k16 = 0; k16 < 8; k16++) {
        unsigned ah[4], al[4];
        int kp = k16 * 8 + c0;
        ah[0] = sph[r0][kp];     ah[1] = sph[r0 + 8][kp];
        ah[2] = sph[r0][kp + 4]; ah[3] = sph[r0 + 8][kp + 4];
        al[0] = spl[r0][kp];     al[1] = spl[r0 + 8][kp];
        al[2] = spl[r0][kp + 4]; al[3] = spl[r0 + 8][kp + 4];
        #pragma unroll
        for (int j = 0; j < 12; j++) {
            int nt = (j >> 2) * 16 + w * 4 + (j & 3);
            uint4 bvv = g_Bgi[(nt * 8 + k16) * 32 + l];
            mma16(acc[j], ah, bvv.x, bvv.y);
            mma16(acc[j], al, bvv.x, bvv.y);
            mma16(acc[j], ah, bvv.z, bvv.w);
        }
    }
    #pragma unroll
    for (int j = 0; j < 12; j++)
        #pragma unroll
        for (int x = 0; x < 4; x++) sgi[t][j * 4 + x] = acc[j][x];

    #pragma unroll
    for (int j = 0; j < 12; j++)
        #pragma unroll
        for (int x = 0; x < 4; x++) acc[j][x] = 0.f;
    #pragma unroll
    for (int k16 = 0; k16 < 8; k16++) {
        unsigned ah[4], al[4];
        int kp = k16 * 8 + c0;
        ah[0] = snh[r0][kp];     ah[1] = snh[r0 + 8][kp];
        ah[2] = snh[r0][kp + 4]; ah[3] = snh[r0 + 8][kp + 4];
        al[0] = snl[r0][kp];     al[1] = snl[r0 + 8][kp];
        al[2] = snl[r0][kp + 4]; al[3] = snl[r0 + 8][kp + 4];
        #pragma unroll
        for (int j = 0; j < 12; j++) {
            int nt = (j >> 2) * 16 + w * 4 + (j & 3);
            uint4 bvv = g_Bgh[(nt * 8 + k16) * 32 + l];
            mma16(acc[j], ah, bvv.x, bvv.y);
            mma16(acc[j], al, bvv.x, bvv.y);
            mma16(acc[j], ah, bvv.z, bvv.w);
        }
    }

    float G0 = g_G[base + r0], G1 = g_G[base + r0 + 8];
    #pragma unroll
    for (int j = 0; j < 4; j++) {
        int colg = w * 32 + j * 8 + 2 * c0;
        float2 o0, o1;
        #pragma unroll
        for (int b = 0; b < 2; b++) {
            int col = colg + b;
            float bfr = g_bf[col], bfz = g_bf[128 + col], bfn = g_bf[256 + col];
            float bir = bih[col], biz = bih[128 + col], bin = bih[256 + col];
            float bhr = bhh[col], bhz = bhh[128 + col], bhn = bhh[256 + col];
            {
                float gir = sgi[t][j * 4 + b]       + bir + G0 * bfr;
                float giz = sgi[t][(j + 4) * 4 + b] + biz + G0 * bfz;
                float gin = sgi[t][(j + 8) * 4 + b] + bin + G0 * bfn;
                float ghr = acc[j][b] + bhr, ghz = acc[j + 4][b] + bhz, ghn = acc[j + 8][b] + bhn;
                float rr = fsig(gir + ghr), zz = fsig(giz + ghz);
                float nv = ftanh(gin + rr * ghn);
                float xo = (1.f - zz) * nv + zz * snraw[r0][col];
                if (b) o0.y = xo; else o0.x = xo;
            }
            {
                float gir = sgi[t][j * 4 + b + 2]       + bir + G1 * bfr;
                float giz = sgi[t][(j + 4) * 4 + b + 2] + biz + G1 * bfz;
                float gin = sgi[t][(j + 8) * 4 + b + 2] + bin + G1 * bfn;
                float ghr = acc[j][b + 2] + bhr, ghz = acc[j + 4][b + 2] + bhz, ghn = acc[j + 8][b + 2] + bhn;
                float rr = fsig(gir + ghr), zz = fsig(giz + ghz);
                float nv = ftanh(gin + rr * ghn);
                float xo = (1.f - zz) * nv + zz * snraw[r0 + 8][col];
                if (b) o1.y = xo; else o1.x = xo;
            }
        }
        *(float2*)&out[(base + r0) * ND + colg]     = o0;
        *(float2*)&out[(base + r0 + 8) * ND + colg] = o1;
    }
}

extern "C" void kernel_launch(void* const* d_in, const int* in_sizes, int n_in,
                              void* d_out, int out_size) {
    const float* nf  = (const float*)d_in[0];
    const int*   ei  = (const int*)d_in[1];
    const float* ef  = (const float*)d_in[2];
    const float* W1  = (const float*)d_in[3];
    const float* b1  = (const float*)d_in[4];
    const float* lng = (const float*)d_in[5];
    const float* lnb = (const float*)d_in[6];
    const float* W2  = (const float*)d_in[7];
    const float* b2  = (const float*)d_in[8];
    const float* gw  = (const float*)d_in[9];
    const float* gb  = (const float*)d_in[10];
    const float* Wih = (const float*)d_in[11];
    const float* bih = (const float*)d_in[12];
    const float* Whh = (const float*)d_in[13];
    const float* bhh = (const float*)d_in[14];
    float* out = (float*)d_out;

    k_zero<<<(NN * ND / 4 + 255) / 256, 256>>>();
    k_transH<<<(384 * ND + 255) / 256, 256>>>(Whh);
    k_fold<<<ND, 384>>>(W2, Wih, b2);
    k_prep<<<128, 256>>>(W1);
    k_nodeAB_t<<<NN / 32, 128>>>(nf);
    k_edge<<<2368, 128>>>(ef, ei, W1, b1, lng, lnb, gw, gb);
    k_gru_t<<<NN / 16, 128>>>(nf, bih, bhh, out);
}